// round 14
// baseline (speedup 1.0000x reference)
#include <cuda_runtime.h>
#include <cstdint>

// out[b,f,m] = floor(log2( sum_h (x+1)^2 * fb[m,h] )), h<257
// mma.sync m16n8k8 TF32 3-pass emulation over k=0..255, k=256 exact in epilogue.
// TPB=512, M16xN32 warp tile, 2 CTAs/SM, persistent + ticket.
// A pre-split (mag -> tf32 hi/lo) into smem once per chunk by a transform phase.

#define KREAL   257
#define NMELS   64
#define XSTR    512
#define MTILE   128
#define TPB     512
#define NCHUNK  8
#define NTILES  512
#define GRID    296

#define RAWROW  36                           // raw row stride (floats), 144B
#define RAW_BYTES (MTILE * RAWROW * 4)       // 18432
#define ASPLIT_F4 2048                       // [t(4)][mGrp(8)][half(2)][lane(32)] f4
#define ASPLIT_BYTES (ASPLIT_F4 * 16)        // 32768
#define B_F4    1024                         // [t(4)][nt(8)][lane(32)] float4
#define B_BYTES (B_F4 * 16)                  // 16384 per buffer
#define RAW_OFF    0
#define ASPLIT_OFF RAW_BYTES                 // 18432
#define B_OFF      (ASPLIT_OFF + ASPLIT_BYTES)      // 51200
#define EDGE_OFF   (B_OFF + 2 * B_BYTES)            // 83968
#define SMEM_BYTES (EDGE_OFF + (MTILE + NMELS) * 4) // 84736 -> 2 CTAs/SM

__device__ float4 g_fbFrag[NCHUNK * B_F4];
__device__ unsigned g_ticket;

__device__ __forceinline__ float tf32_hi(float v) {
    unsigned h;
    asm("cvt.rna.tf32.f32 %0, %1;" : "=r"(h) : "f"(v));
    return __uint_as_float(h);
}
__device__ __forceinline__ unsigned smem_u32(const void* p) {
    unsigned a;
    asm("{ .reg .u64 t; cvta.to.shared.u64 t, %1; cvt.u32.u64 %0, t; }" : "=r"(a) : "l"(p));
    return a;
}
#define CP_ASYNC16(dst, src) \
    asm volatile("cp.async.ca.shared.global [%0], [%1], 16;" :: "r"(dst), "l"(src))
#define CP_COMMIT() asm volatile("cp.async.commit_group;" ::: "memory")
#define CP_WAIT0()  asm volatile("cp.async.wait_group 0;" ::: "memory")

__device__ __forceinline__ void mma8(float* d,
                                     float a0, float a1, float a2, float a3,
                                     float b0, float b1) {
    asm volatile(
        "mma.sync.aligned.m16n8k8.row.col.f32.tf32.tf32.f32 "
        "{%0,%1,%2,%3}, {%4,%5,%6,%7}, {%8,%9}, {%0,%1,%2,%3};"
        : "+f"(d[0]), "+f"(d[1]), "+f"(d[2]), "+f"(d[3])
        : "r"(__float_as_uint(a0)), "r"(__float_as_uint(a1)),
          "r"(__float_as_uint(a2)), "r"(__float_as_uint(a3)),
          "r"(__float_as_uint(b0)), "r"(__float_as_uint(b1)));
}

// ---- prep: fb -> fragment float4 (b0hi,b0lo,b1hi,b1lo); also resets ticket ----
__global__ void prep_kernel(const float* __restrict__ fb) {
    if (blockIdx.x == 0 && threadIdx.x == 0) g_ticket = GRID;
    int ch = blockIdx.x;
    for (int i = threadIdx.x; i < B_F4; i += blockDim.x) {
        int lane = i & 31;
        int nt   = (i >> 5) & 7;
        int t    = (i >> 8) & 3;
        int n  = nt * 8 + (lane >> 2);
        int k0 = ch * 32 + t * 8 + (lane & 3);
        float v0 = fb[n * KREAL + k0];
        float v1 = fb[n * KREAL + k0 + 4];
        float h0 = tf32_hi(v0), h1 = tf32_hi(v1);
        g_fbFrag[ch * B_F4 + i] = make_float4(h0, v0 - h0, h1, v1 - h1);
    }
}

__global__ void __launch_bounds__(TPB, 2)
lmfe_kernel(const float* __restrict__ x, const float* __restrict__ fb,
            float* __restrict__ out) {
    extern __shared__ char smemRaw[];
    float*  sRaw   = reinterpret_cast<float*>(smemRaw + RAW_OFF);     // [128][36]
    float4* sASp   = reinterpret_cast<float4*>(smemRaw + ASPLIT_OFF); // [2048] f4
    float4* sB     = reinterpret_cast<float4*>(smemRaw + B_OFF);      // [2][1024] f4
    float*  sMag   = reinterpret_cast<float*>(smemRaw + EDGE_OFF);    // [128]
    float*  sFbc   = sMag + MTILE;                                    // [64]
    __shared__ unsigned sTile;
    const unsigned rawAddr = smem_u32(sRaw);
    const unsigned sBaddr  = smem_u32(sB);

    const int tid  = threadIdx.x;
    const int wid  = tid >> 5;
    const int lane = tid & 31;

    if (tid < NMELS) sFbc[tid] = fb[tid * KREAL + 256];

    // staging/transform map: thread -> (row = tid>>2, t = tid&3), 8 floats
    const int aRow = tid >> 2;
    const int aT   = tid & 3;
    const unsigned rawDst = rawAddr + (aRow * RAWROW + aT * 8) * 4;
    const float* rawRd = sRaw + aRow * RAWROW + aT * 8;
    // split write base: f4 idx = aT*512 + mg*64 + hf*32 + gg*4
    float4* spWr = sASp + aT * 512 + (aRow >> 4) * 64 + ((aRow >> 3) & 1) * 32 +
                   (aRow & 7) * 4;
    const float4* bSrcBase = g_fbFrag + tid;    // + ch*B_F4 + p*TPB, p<2

    // warp tile map: M16 (mGrp=wid&7) x N32 (nHalf=wid>>3)
    const int mGrp  = wid & 7;
    const int nHalf = wid >> 3;
    const int g   = lane >> 2;
    const int tig = lane & 3;
    const int row0L = mGrp * 16 + g;
    const int col0  = nHalf * 32 + 2 * tig;
    const float4* aRd = sASp + mGrp * 64 + lane;   // + t*512 ; +32 for half1

    unsigned tile = blockIdx.x;

#pragma unroll 1
    while (tile < NTILES) {
        const size_t rowBase = (size_t)tile * MTILE;
        const float* xp = x + (rowBase + (size_t)aRow) * XSTR + aT * 8;

        // ---- stage raw(0) + B(0) + mag256 ----
        CP_ASYNC16(rawDst,      (const void*)xp);
        CP_ASYNC16(rawDst + 16, (const void*)(xp + 4));
        CP_ASYNC16(sBaddr + tid * 16,         (const void*)bSrcBase);
        CP_ASYNC16(sBaddr + (tid + TPB) * 16, (const void*)(bSrcBase + TPB));
        CP_COMMIT();
        if (tid < MTILE) {
            float v = x[(rowBase + (size_t)tid) * XSTR + 256] + 1.0f;
            sMag[tid] = v * v;
        }
        CP_WAIT0();
        __syncthreads();

        float acc[4][4];
#pragma unroll
        for (int nt = 0; nt < 4; ++nt)
#pragma unroll
            for (int r = 0; r < 4; ++r) acc[nt][r] = 0.0f;

#pragma unroll 1
        for (int ch = 0; ch < NCHUNK; ++ch) {
            // ---- transform phase: raw(ch) -> splitA ----
            {
                float4 v0 = *reinterpret_cast<const float4*>(rawRd);
                float4 v1 = *reinterpret_cast<const float4*>(rawRd + 4);
                float m[8], h[8];
                m[0]=(v0.x+1.f)*(v0.x+1.f); m[1]=(v0.y+1.f)*(v0.y+1.f);
                m[2]=(v0.z+1.f)*(v0.z+1.f); m[3]=(v0.w+1.f)*(v0.w+1.f);
                m[4]=(v1.x+1.f)*(v1.x+1.f); m[5]=(v1.y+1.f)*(v1.y+1.f);
                m[6]=(v1.z+1.f)*(v1.z+1.f); m[7]=(v1.w+1.f)*(v1.w+1.f);
#pragma unroll
                for (int i = 0; i < 8; ++i) h[i] = tf32_hi(m[i]);
                spWr[0] = make_float4(h[0], m[0]-h[0], h[4], m[4]-h[4]);
                spWr[1] = make_float4(h[1], m[1]-h[1], h[5], m[5]-h[5]);
                spWr[2] = make_float4(h[2], m[2]-h[2], h[6], m[6]-h[6]);
                spWr[3] = make_float4(h[3], m[3]-h[3], h[7], m[7]-h[7]);
            }
            __syncthreads();   // splitA ready; raw free

            if (ch + 1 < NCHUNK) {
                // raw(ch+1) into the (now free) raw buffer
                const float* aS = xp + (ch + 1) * 32;
                CP_ASYNC16(rawDst,      (const void*)aS);
                CP_ASYNC16(rawDst + 16, (const void*)(aS + 4));
                // B(ch+1) into buffer (ch+1)&1
                const unsigned bD = sBaddr + ((ch + 1) & 1) * B_BYTES;
                const float4* bS = bSrcBase + (ch + 1) * B_F4;
                CP_ASYNC16(bD + tid * 16,         (const void*)bS);
                CP_ASYNC16(bD + (tid + TPB) * 16, (const void*)(bS + TPB));
                CP_COMMIT();
            }

            // ---- MMA phase ----
            const float4* bBuf = sB + (ch & 1) * B_F4 + nHalf * 128 + lane;
#pragma unroll
            for (int t = 0; t < 4; ++t) {
                float4 A0 = aRd[t * 512];        // (a0h,a0l,a2h,a2l) rows g
                float4 A1 = aRd[t * 512 + 32];   // (a1h,a1l,a3h,a3l) rows g+8
                float4 b0 = bBuf[t * 256];
                float4 b1 = bBuf[t * 256 + 32];
                float4 b2 = bBuf[t * 256 + 64];
                float4 b3 = bBuf[t * 256 + 96];
                mma8(acc[0], A0.x, A1.x, A0.z, A1.z, b0.x, b0.z);
                mma8(acc[1], A0.x, A1.x, A0.z, A1.z, b1.x, b1.z);
                mma8(acc[2], A0.x, A1.x, A0.z, A1.z, b2.x, b2.z);
                mma8(acc[3], A0.x, A1.x, A0.z, A1.z, b3.x, b3.z);
                mma8(acc[0], A0.x, A1.x, A0.z, A1.z, b0.y, b0.w);
                mma8(acc[1], A0.x, A1.x, A0.z, A1.z, b1.y, b1.w);
                mma8(acc[2], A0.x, A1.x, A0.z, A1.z, b2.y, b2.w);
                mma8(acc[3], A0.x, A1.x, A0.z, A1.z, b3.y, b3.w);
                mma8(acc[0], A0.y, A1.y, A0.w, A1.w, b0.x, b0.z);
                mma8(acc[1], A0.y, A1.y, A0.w, A1.w, b1.x, b1.z);
                mma8(acc[2], A0.y, A1.y, A0.w, A1.w, b2.x, b2.z);
                mma8(acc[3], A0.y, A1.y, A0.w, A1.w, b3.x, b3.z);
            }

            if (ch + 1 < NCHUNK) CP_WAIT0();
            __syncthreads();
        }

        // ---- epilogue: exact k=256 term + exponent extract ----
        const float a0m = sMag[row0L];
        const float a1m = sMag[row0L + 8];
        const size_t r0w = rowBase + (size_t)row0L;
#pragma unroll
        for (int nt = 0; nt < 4; ++nt) {
            float2 fc = *reinterpret_cast<const float2*>(sFbc + col0 + nt * 8);
            float v00 = fmaf(a0m, fc.x, acc[nt][0]);
            float v01 = fmaf(a0m, fc.y, acc[nt][1]);
            float v10 = fmaf(a1m, fc.x, acc[nt][2]);
            float v11 = fmaf(a1m, fc.y, acc[nt][3]);
            float2 o0, o1;
            o0.x = (float)(int)(((__float_as_uint(v00) >> 23) & 0xFF) - 127);
            o0.y = (float)(int)(((__float_as_uint(v01) >> 23) & 0xFF) - 127);
            o1.x = (float)(int)(((__float_as_uint(v10) >> 23) & 0xFF) - 127);
            o1.y = (float)(int)(((__float_as_uint(v11) >> 23) & 0xFF) - 127);
            *reinterpret_cast<float2*>(out + r0w * NMELS + col0 + nt * 8)       = o0;
            *reinterpret_cast<float2*>(out + (r0w + 8) * NMELS + col0 + nt * 8) = o1;
        }

        // ---- next tile via ticket ----
        __syncthreads();
        if (tid == 0) sTile = atomicAdd(&g_ticket, 1u);
        __syncthreads();
        tile = sTile;
    }
}

extern "C" void kernel_launch(void* const* d_in, const int* in_sizes, int n_in,
                              void* d_out, int out_size) {
    const float* x  = (const float*)d_in[0];   // (256,256,512,1) fp32
    const float* fb = (const float*)d_in[1];   // (64,257) fp32
    float* out = (float*)d_out;                // (256,256,64,1) fp32

    prep_kernel<<<NCHUNK, 256>>>(fb);          // also resets the tile ticket

    cudaFuncSetAttribute(lmfe_kernel,
                         cudaFuncAttributeMaxDynamicSharedMemorySize, SMEM_BYTES);
    lmfe_kernel<<<GRID, TPB, SMEM_BYTES>>>(x, fb, out);
}